// round 12
// baseline (speedup 1.0000x reference)
#include <cuda_runtime.h>
#include <cuda_fp16.h>
#include <cstdint>

#define NCHUNK 36            // 2304 / 64
#define STAGE  49152         // A 16KB + B 32KB
#define NSTG   4
#define SMEM_TOTAL (NSTG * STAGE)   // 196608

// ---------------- device scratch ----------------
__device__ float g_T[256 * 256];
__device__ float g_scale[8 * 256];
__device__ __align__(16) __half g_wpack[NCHUNK * 2 * 8192];      // [chunk][ocT][8192] pre-swizzled fp16
__device__ __align__(16) __half g_xh[8 * 128 * 128 * 256];       // [b][h][w][ic] fp16, code folded

// ---------------- helpers ----------------
__device__ __forceinline__ uint32_t smem_u32(const void* p) {
    uint32_t a;
    asm("{ .reg .u64 t; cvta.to.shared.u64 t, %1; cvt.u32.u64 %0, t; }" : "=r"(a) : "l"(p));
    return a;
}
#define SWZ128(o) ((o) ^ (((o) >> 3) & 0x70))

__device__ __forceinline__ void cp16(uint32_t dst, const void* src, int sz) {
    asm volatile("cp.async.cg.shared.global [%0], [%1], 16, %2;\n"
                 :: "r"(dst), "l"(src), "r"(sz) : "memory");
}
#define CP_COMMIT() asm volatile("cp.async.commit_group;" ::: "memory")
#define CP_WAIT2()  asm volatile("cp.async.wait_group 2;" ::: "memory")

#define LDSM4(r0, r1, r2, r3, addr) \
    asm volatile("ldmatrix.sync.aligned.m8n8.x4.shared.b16 {%0,%1,%2,%3}, [%4];" \
                 : "=r"(r0), "=r"(r1), "=r"(r2), "=r"(r3) : "r"(addr))

#define MMA16816(c, a0, a1, a2, a3, b0, b1) \
    asm volatile("mma.sync.aligned.m16n8k16.row.col.f32.f16.f16.f32 " \
                 "{%0,%1,%2,%3}, {%4,%5,%6,%7}, {%8,%9}, {%0,%1,%2,%3};" \
                 : "+f"((c)[0]), "+f"((c)[1]), "+f"((c)[2]), "+f"((c)[3]) \
                 : "r"(a0), "r"(a1), "r"(a2), "r"(a3), "r"(b0), "r"(b1))

// ---------------- prep kernels ----------------
// pack_w + tsum fused (keeps conv at our launch #4 = ncu capture slot)
__global__ void pack_w_kernel(const float* __restrict__ w) {
    int id = blockIdx.x * 256 + threadIdx.x;   // 0 .. 589823
    int chunk = id >> 14;
    int kk    = (id >> 8) & 63;
    int oc    = id & 255;
    int ocT = oc >> 7, m = oc & 127;
    float v = w[(chunk * 64 + kk) * 256 + oc];
    int sw = SWZ128(m * 128 + kk * 2) >> 1;
    g_wpack[(chunk * 2 + ocT) * 8192 + sw] = __float2half(v);
    // tsum duty for first 256 blocks: T[ic*256+oc] = sum_tap W^2  (L2-hot rereads)
    if (blockIdx.x < 256) {
        int idx = blockIdx.x * 256 + threadIdx.x;   // ic*256 + oc
        float s = 0.f;
#pragma unroll
        for (int tap = 0; tap < 9; tap++) { float t = w[tap * 65536 + idx]; s += t * t; }
        g_T[idx] = s;
    }
}

__global__ void scale_kernel(const float* __restrict__ code) {
    __shared__ float c2[256];
    int b = blockIdx.x, oc = threadIdx.x;
    float c = code[b * 256 + oc];
    c2[oc] = c * c;
    __syncthreads();
    float s = 0.f;
#pragma unroll 8
    for (int ic = 0; ic < 256; ic++) s += g_T[ic * 256 + oc] * c2[ic];
    const float wscale = 1.0f / 48.0f, wscale2 = 1.0f / 2304.0f;
    g_scale[b * 256 + oc] = wscale * rsqrtf(wscale2 * s + 1e-8f);
}

// x[b][ic][h][w] * code -> g_xh [b][h][w][ic] fp16, vectorized transpose
__global__ __launch_bounds__(256)
void xt_kernel(const float* __restrict__ x, const float* __restrict__ code) {
    __shared__ float st[64][129];
    int bh = blockIdx.x;
    int b = bh >> 7, h = bh & 127;
    int tid = threadIdx.x;
    const int icp = tid & 31;
    for (int sub = 0; sub < 4; sub++) {
        int icB = sub * 64;
#pragma unroll
        for (int i = 0; i < 8; i++) {
            int lin = tid + 256 * i;
            int r = lin >> 5, c4 = (lin & 31) * 4;
            float4 v = *(const float4*)&x[((size_t)(b * 256 + icB + r)) * 16384 + h * 128 + c4];
            st[r][c4 + 0] = v.x;
            st[r][c4 + 1] = v.y;
            st[r][c4 + 2] = v.z;
            st[r][c4 + 3] = v.w;
        }
        __syncthreads();
        int ic0 = icB + icp * 2;
        float c0 = __ldg(&code[b * 256 + ic0]);
        float c1 = __ldg(&code[b * 256 + ic0 + 1]);
#pragma unroll
        for (int i = 0; i < 16; i++) {
            int lin = tid + 256 * i;
            int w = lin >> 5;
            __half2 hv = __floats2half2_rn(st[icp * 2][w] * c0, st[icp * 2 + 1][w] * c1);
            *(__half2*)&g_xh[((size_t)bh * 128 + w) * 256 + ic0] = hv;
        }
        __syncthreads();
    }
}

// ------- main conv: 128 oc x 256 px, 256 thr, 8 warps of 64oc x 64px -------
__device__ __forceinline__ void load_chunk(int chunk, uint32_t st, int b, int h0, int tid, int ocT) {
    // A: 16KB pre-swizzled linear copy (1024 cp16, 4/thread)
    const __half* wsrc = g_wpack + ((size_t)chunk * 2 + ocT) * 8192;
#pragma unroll
    for (int i = 0; i < 4; i++) {
        int u = tid + i * 256;               // 0..1023
        cp16(st + u * 16, wsrc + u * 8, 16);
    }
    // B: 256 pixel-rows x 128B of 64 ic (2048 cp16, 8/thread)
    int tap = chunk >> 2;
    int icB = (chunk & 3) * 64;
    int dtap = tap / 3;
    int dh = dtap - 1, dw = tap - 3 * dtap - 1;
    const __half* xb = g_xh + (size_t)b * 128 * 128 * 256 + icB;
#pragma unroll
    for (int i = 0; i < 8; i++) {
        int u = tid + i * 256;               // 0..2047
        int p = u >> 3, j = u & 7;           // p in [0,256)
        int hh = h0 + (p >> 7) + dh;
        int ws = (p & 127) + dw;
        bool ok = ((unsigned)hh < 128u) && ((unsigned)ws < 128u);
        const __half* src = xb + ((size_t)(ok ? hh : 0) * 128 + (ok ? ws : 0)) * 256 + j * 8;
        cp16(st + 16384 + SWZ128(p * 128 + j * 16), src, ok ? 16 : 0);
    }
}

__global__ __launch_bounds__(256, 1)
void conv_mma_kernel(const float* __restrict__ bias, float* __restrict__ out) {
    extern __shared__ char smem[];
    uint32_t sb = smem_u32(smem);
    const int tid = threadIdx.x;
    const int lane = tid & 31, wid = tid >> 5;     // 8 warps
    const int b  = blockIdx.x >> 6;
    const int h0 = (blockIdx.x & 63) * 2;
    const int ocT = blockIdx.y;

    const int mbase = (wid & 1) * 64;              // oc within 128 (2 m-warps)
    const int nbase = (wid >> 1) * 64;             // pixel within 256 (4 n-warps)
    const uint32_t xm = (lane & 7) << 4;
    const uint32_t aksel = (lane >> 4) * 16;
    const uint32_t bksel = ((lane >> 3) & 1) * 16;
    uint32_t arow[4];
#pragma unroll
    for (int mi = 0; mi < 4; mi++)
        arow[mi] = (uint32_t)(mbase + mi * 16 + (lane & 15)) * 128;
    uint32_t brow[4];
#pragma unroll
    for (int nj = 0; nj < 4; nj++)
        brow[nj] = (uint32_t)(nbase + nj * 16 + (lane >> 4) * 8 + (lane & 7)) * 128;

    float acc[4][8][4];
#pragma unroll
    for (int mi = 0; mi < 4; mi++)
#pragma unroll
        for (int nt = 0; nt < 8; nt++)
#pragma unroll
            for (int q = 0; q < 4; q++) acc[mi][nt][q] = 0.f;

    // prologue: 3 stages
#pragma unroll
    for (int s = 0; s < 3; s++) {
        load_chunk(s, sb + s * STAGE, b, h0, tid, ocT);
        CP_COMMIT();
    }

    for (int c = 0; c < NCHUNK; c++) {
        CP_WAIT2();
        __syncthreads();
        if (c + 3 < NCHUNK)
            load_chunk(c + 3, sb + ((c + 3) & 3) * STAGE, b, h0, tid, ocT);
        CP_COMMIT();   // unconditional: keeps wait_group invariant at tail

        const uint32_t st = sb + (c & 3) * STAGE;
        const uint32_t Ab = st;
        const uint32_t Bb = st + 16384;
#pragma unroll
        for (int ks = 0; ks < 4; ks++) {
            const uint32_t kb = ks * 32;
            uint32_t bf[4][4];
#pragma unroll
            for (int nj = 0; nj < 4; nj++)
                LDSM4(bf[nj][0], bf[nj][1], bf[nj][2], bf[nj][3],
                      Bb + brow[nj] + ((kb + bksel) ^ xm));
#pragma unroll
            for (int mi = 0; mi < 4; mi++) {
                uint32_t a0, a1, a2, a3;
                LDSM4(a0, a1, a2, a3,
                      Ab + arow[mi] + ((kb + aksel) ^ xm));
#pragma unroll
                for (int nj = 0; nj < 4; nj++) {
                    MMA16816(acc[mi][nj * 2 + 0], a0, a1, a2, a3, bf[nj][0], bf[nj][1]);
                    MMA16816(acc[mi][nj * 2 + 1], a0, a1, a2, a3, bf[nj][2], bf[nj][3]);
                }
            }
        }
    }

    // epilogue: demod scale + bias + LeakyReLU(0.2)*sqrt(2)
    const float ACT = 1.4142135623730951f;
    const int r0 = lane >> 2;
    const int cpix = (lane & 3) * 2;
    const int hh = h0 + (nbase >> 7);        // warp's 64 px lie in one h row
    const int wb = nbase & 127;
#pragma unroll
    for (int mi = 0; mi < 4; mi++) {
        int ocb = ocT * 128 + mbase + mi * 16;
        int oc0 = ocb + r0, oc1 = oc0 + 8;
        float s0 = g_scale[b * 256 + oc0], bi0 = bias[oc0];
        float s1 = g_scale[b * 256 + oc1], bi1 = bias[oc1];
        float* o0 = out + ((size_t)(b * 256 + oc0)) * 16384 + hh * 128 + wb;
        float* o1 = out + ((size_t)(b * 256 + oc1)) * 16384 + hh * 128 + wb;
#pragma unroll
        for (int nt = 0; nt < 8; nt++) {
            int w = nt * 8 + cpix;
            float t0 = acc[mi][nt][0] * s0 + bi0;
            float t1 = acc[mi][nt][1] * s0 + bi0;
            float t2 = acc[mi][nt][2] * s1 + bi1;
            float t3 = acc[mi][nt][3] * s1 + bi1;
            float2 v0, v1;
            v0.x = (t0 >= 0.f ? t0 : 0.2f * t0) * ACT;
            v0.y = (t1 >= 0.f ? t1 : 0.2f * t1) * ACT;
            v1.x = (t2 >= 0.f ? t2 : 0.2f * t2) * ACT;
            v1.y = (t3 >= 0.f ? t3 : 0.2f * t3) * ACT;
            *(float2*)(o0 + w) = v0;
            *(float2*)(o1 + w) = v1;
        }
    }
}

// ---------------- launch ----------------
extern "C" void kernel_launch(void* const* d_in, const int* in_sizes, int n_in,
                              void* d_out, int out_size) {
    const float* x      = (const float*)d_in[0];
    const float* code   = (const float*)d_in[1];
    const float* weight = (const float*)d_in[2];
    const float* bias   = (const float*)d_in[3];
    float* out = (float*)d_out;

    cudaFuncSetAttribute(conv_mma_kernel, cudaFuncAttributeMaxDynamicSharedMemorySize, SMEM_TOTAL);

    pack_w_kernel<<<2304, 256>>>(weight);     // includes fused tsum
    scale_kernel<<<8, 256>>>(code);
    xt_kernel<<<1024, 256>>>(x, code);
    conv_mma_kernel<<<dim3(512, 2), 256, SMEM_TOTAL>>>(bias, out);  // launch #4 -> ncu slot
}

// round 13
// speedup vs baseline: 1.0977x; 1.0977x over previous
#include <cuda_runtime.h>
#include <cuda_fp16.h>
#include <cstdint>

#define NCHUNK 36            // 2304 / 64
#define STAGE  32768         // A 16KB + B 16KB
#define NSTG   3
#define SMEM_TOTAL (NSTG * STAGE)   // 98304 -> 2 CTAs/SM

// ---------------- device scratch ----------------
__device__ float g_T[256 * 256];
__device__ float g_scale[8 * 256];
__device__ __align__(16) __half g_wpack[NCHUNK * 2 * 8192];      // [chunk][ocT][8192] pre-swizzled fp16
__device__ __align__(16) __half g_xh[8 * 128 * 128 * 256];       // [b][h][w][ic] fp16, code folded

// ---------------- helpers ----------------
__device__ __forceinline__ uint32_t smem_u32(const void* p) {
    uint32_t a;
    asm("{ .reg .u64 t; cvta.to.shared.u64 t, %1; cvt.u32.u64 %0, t; }" : "=r"(a) : "l"(p));
    return a;
}
#define SWZ128(o) ((o) ^ (((o) >> 3) & 0x70))

__device__ __forceinline__ void cp16(uint32_t dst, const void* src, int sz) {
    asm volatile("cp.async.cg.shared.global [%0], [%1], 16, %2;\n"
                 :: "r"(dst), "l"(src), "r"(sz) : "memory");
}
#define CP_COMMIT() asm volatile("cp.async.commit_group;" ::: "memory")
#define CP_WAIT1()  asm volatile("cp.async.wait_group 1;" ::: "memory")

#define LDSM4(r0, r1, r2, r3, addr) \
    asm volatile("ldmatrix.sync.aligned.m8n8.x4.shared.b16 {%0,%1,%2,%3}, [%4];" \
                 : "=r"(r0), "=r"(r1), "=r"(r2), "=r"(r3) : "r"(addr))

#define MMA16816(c, a0, a1, a2, a3, b0, b1) \
    asm volatile("mma.sync.aligned.m16n8k16.row.col.f32.f16.f16.f32 " \
                 "{%0,%1,%2,%3}, {%4,%5,%6,%7}, {%8,%9}, {%0,%1,%2,%3};" \
                 : "+f"((c)[0]), "+f"((c)[1]), "+f"((c)[2]), "+f"((c)[3]) \
                 : "r"(a0), "r"(a1), "r"(a2), "r"(a3), "r"(b0), "r"(b1))

// ---------------- prep kernels ----------------
// pack_w + tsum fused (keeps conv at our launch #4 = ncu capture slot)
__global__ void pack_w_kernel(const float* __restrict__ w) {
    int id = blockIdx.x * 256 + threadIdx.x;   // 0 .. 589823
    int chunk = id >> 14;
    int kk    = (id >> 8) & 63;
    int oc    = id & 255;
    int ocT = oc >> 7, m = oc & 127;
    float v = w[(chunk * 64 + kk) * 256 + oc];
    int sw = SWZ128(m * 128 + kk * 2) >> 1;
    g_wpack[(chunk * 2 + ocT) * 8192 + sw] = __float2half(v);
    if (blockIdx.x < 256) {
        int idx = blockIdx.x * 256 + threadIdx.x;   // ic*256 + oc
        float s = 0.f;
#pragma unroll
        for (int tap = 0; tap < 9; tap++) { float t = w[tap * 65536 + idx]; s += t * t; }
        g_T[idx] = s;
    }
}

__global__ void scale_kernel(const float* __restrict__ code) {
    __shared__ float c2[256];
    int b = blockIdx.x, oc = threadIdx.x;
    float c = code[b * 256 + oc];
    c2[oc] = c * c;
    __syncthreads();
    float s = 0.f;
#pragma unroll 8
    for (int ic = 0; ic < 256; ic++) s += g_T[ic * 256 + oc] * c2[ic];
    const float wscale = 1.0f / 48.0f, wscale2 = 1.0f / 2304.0f;
    g_scale[b * 256 + oc] = wscale * rsqrtf(wscale2 * s + 1e-8f);
}

// x[b][ic][h][w] * code -> g_xh [b][h][w][ic] fp16, vectorized transpose
__global__ __launch_bounds__(256)
void xt_kernel(const float* __restrict__ x, const float* __restrict__ code) {
    __shared__ float st[64][129];
    int bh = blockIdx.x;
    int b = bh >> 7, h = bh & 127;
    int tid = threadIdx.x;
    const int icp = tid & 31;
    for (int sub = 0; sub < 4; sub++) {
        int icB = sub * 64;
#pragma unroll
        for (int i = 0; i < 8; i++) {
            int lin = tid + 256 * i;
            int r = lin >> 5, c4 = (lin & 31) * 4;
            float4 v = *(const float4*)&x[((size_t)(b * 256 + icB + r)) * 16384 + h * 128 + c4];
            st[r][c4 + 0] = v.x;
            st[r][c4 + 1] = v.y;
            st[r][c4 + 2] = v.z;
            st[r][c4 + 3] = v.w;
        }
        __syncthreads();
        int ic0 = icB + icp * 2;
        float c0 = __ldg(&code[b * 256 + ic0]);
        float c1 = __ldg(&code[b * 256 + ic0 + 1]);
#pragma unroll
        for (int i = 0; i < 16; i++) {
            int lin = tid + 256 * i;
            int w = lin >> 5;
            __half2 hv = __floats2half2_rn(st[icp * 2][w] * c0, st[icp * 2 + 1][w] * c1);
            *(__half2*)&g_xh[((size_t)bh * 128 + w) * 256 + ic0] = hv;
        }
        __syncthreads();
    }
}

// ------- main conv: 128 oc x 128 px (one h row), 256 thr, 2 CTAs/SM -------
__device__ __forceinline__ void load_chunk(int chunk, uint32_t st, int b, int h, int tid, int ocT) {
    // A: 16KB pre-swizzled linear copy (1024 cp16, 4/thread)
    const __half* wsrc = g_wpack + ((size_t)chunk * 2 + ocT) * 8192;
#pragma unroll
    for (int i = 0; i < 4; i++) {
        int u = tid + i * 256;               // 0..1023
        cp16(st + u * 16, wsrc + u * 8, 16);
    }
    // B: 128 pixel-rows x 128B of 64 ic (1024 cp16, 4/thread)
    int tap = chunk >> 2;
    int icB = (chunk & 3) * 64;
    int dtap = tap / 3;
    int dh = dtap - 1, dw = tap - 3 * dtap - 1;
    int hh = h + dh;
    bool rok = (unsigned)hh < 128u;
    const __half* xrow = g_xh + ((size_t)(b * 128 + (rok ? hh : 0)) * 128) * 256 + icB;
#pragma unroll
    for (int i = 0; i < 4; i++) {
        int u = tid + i * 256;               // 0..1023
        int r = u >> 3, j = u & 7;
        int ws = r + dw;
        bool ok = rok && ((unsigned)ws < 128u);
        const __half* src = xrow + (size_t)(ok ? ws : 0) * 256 + j * 8;
        cp16(st + 16384 + SWZ128(r * 128 + j * 16), src, ok ? 16 : 0);
    }
}

__global__ __launch_bounds__(256, 2)
void conv_mma_kernel(const float* __restrict__ bias, float* __restrict__ out) {
    extern __shared__ char smem[];
    uint32_t sb = smem_u32(smem);
    const int tid = threadIdx.x;
    const int lane = tid & 31, wid = tid >> 5;     // 8 warps: 4m x 2n
    const int bh = blockIdx.x;
    const int b = bh >> 7, h = bh & 127;
    const int ocT = blockIdx.y;

    const int mbase = (wid & 3) * 32;              // oc within 128
    const int nbase = (wid >> 2) * 64;             // pixel within 128
    const uint32_t xm = (lane & 7) << 4;
    const uint32_t arow0 = (uint32_t)(mbase + (lane & 15)) * 128;
    const uint32_t arow1 = arow0 + 16 * 128;
    const uint32_t aksel = (lane >> 4) * 16;
    const uint32_t bksel = ((lane >> 3) & 1) * 16;
    uint32_t brow[4];
#pragma unroll
    for (int nj = 0; nj < 4; nj++)
        brow[nj] = (uint32_t)(nbase + nj * 16 + (lane >> 4) * 8 + (lane & 7)) * 128;

    float acc[2][8][4];
#pragma unroll
    for (int mi = 0; mi < 2; mi++)
#pragma unroll
        for (int nt = 0; nt < 8; nt++)
#pragma unroll
            for (int q = 0; q < 4; q++) acc[mi][nt][q] = 0.f;

    // prologue: 2 stages
#pragma unroll
    for (int s = 0; s < 2; s++) {
        load_chunk(s, sb + s * STAGE, b, h, tid, ocT);
        CP_COMMIT();
    }

    int slot = 0, nslot = 2;
    for (int c = 0; c < NCHUNK; c++) {
        CP_WAIT1();
        __syncthreads();
        if (c + 2 < NCHUNK)
            load_chunk(c + 2, sb + nslot * STAGE, b, h, tid, ocT);
        CP_COMMIT();   // unconditional: keeps wait_group invariant at tail

        const uint32_t st = sb + slot * STAGE;
        const uint32_t Ab = st;
        const uint32_t Bb = st + 16384;
#pragma unroll
        for (int ks = 0; ks < 4; ks++) {
            const uint32_t kb = ks * 32;
            uint32_t bf[4][4];
#pragma unroll
            for (int nj = 0; nj < 4; nj++)
                LDSM4(bf[nj][0], bf[nj][1], bf[nj][2], bf[nj][3],
                      Bb + brow[nj] + ((kb + bksel) ^ xm));
#pragma unroll
            for (int mi = 0; mi < 2; mi++) {
                uint32_t a0, a1, a2, a3;
                LDSM4(a0, a1, a2, a3,
                      Ab + (mi ? arow1 : arow0) + ((kb + aksel) ^ xm));
#pragma unroll
                for (int nj = 0; nj < 4; nj++) {
                    MMA16816(acc[mi][nj * 2 + 0], a0, a1, a2, a3, bf[nj][0], bf[nj][1]);
                    MMA16816(acc[mi][nj * 2 + 1], a0, a1, a2, a3, bf[nj][2], bf[nj][3]);
                }
            }
        }
        slot = slot == 2 ? 0 : slot + 1;
        nslot = nslot == 2 ? 0 : nslot + 1;
    }

    // epilogue: demod scale + bias + LeakyReLU(0.2)*sqrt(2)
    const float ACT = 1.4142135623730951f;
    const int r0 = lane >> 2;
    const int cpix = (lane & 3) * 2;
#pragma unroll
    for (int mi = 0; mi < 2; mi++) {
        int ocb = ocT * 128 + mbase + mi * 16;
        int oc0 = ocb + r0, oc1 = oc0 + 8;
        float s0 = g_scale[b * 256 + oc0], bi0 = bias[oc0];
        float s1 = g_scale[b * 256 + oc1], bi1 = bias[oc1];
        float* o0 = out + ((size_t)(b * 256 + oc0)) * 16384 + h * 128;
        float* o1 = out + ((size_t)(b * 256 + oc1)) * 16384 + h * 128;
#pragma unroll
        for (int nt = 0; nt < 8; nt++) {
            int w = nbase + nt * 8 + cpix;
            float t0 = acc[mi][nt][0] * s0 + bi0;
            float t1 = acc[mi][nt][1] * s0 + bi0;
            float t2 = acc[mi][nt][2] * s1 + bi1;
            float t3 = acc[mi][nt][3] * s1 + bi1;
            float2 v0, v1;
            v0.x = (t0 >= 0.f ? t0 : 0.2f * t0) * ACT;
            v0.y = (t1 >= 0.f ? t1 : 0.2f * t1) * ACT;
            v1.x = (t2 >= 0.f ? t2 : 0.2f * t2) * ACT;
            v1.y = (t3 >= 0.f ? t3 : 0.2f * t3) * ACT;
            *(float2*)(o0 + w) = v0;
            *(float2*)(o1 + w) = v1;
        }
    }
}

// ---------------- launch ----------------
extern "C" void kernel_launch(void* const* d_in, const int* in_sizes, int n_in,
                              void* d_out, int out_size) {
    const float* x      = (const float*)d_in[0];
    const float* code   = (const float*)d_in[1];
    const float* weight = (const float*)d_in[2];
    const float* bias   = (const float*)d_in[3];
    float* out = (float*)d_out;

    cudaFuncSetAttribute(conv_mma_kernel, cudaFuncAttributeMaxDynamicSharedMemorySize, SMEM_TOTAL);

    pack_w_kernel<<<2304, 256>>>(weight);     // includes fused tsum
    scale_kernel<<<8, 256>>>(code);
    xt_kernel<<<1024, 256>>>(x, code);
    conv_mma_kernel<<<dim3(1024, 2), 256, SMEM_TOTAL>>>(bias, out);  // launch #4 -> ncu slot
}